// round 6
// baseline (speedup 1.0000x reference)
#include <cuda_runtime.h>

#define GDIM 7
#define GG 49
#define NWARPS 8             // one sample per warp

__device__ double   g_acc   = 0.0;
__device__ unsigned g_count = 0u;

__global__ void __launch_bounds__(32 * NWARPS, 5)
loss_fused_kernel(const float* __restrict__ bboxp,   // (N,15,7,7)
                  const float* __restrict__ clsp,    // (N,2)
                  const float* __restrict__ bbox,    // (N,5,7,7)
                  const int*   __restrict__ cls32,   // (N,) int64 as int32 pairs
                  float* __restrict__ out,
                  int N)
{
    const unsigned FULL = 0xffffffffu;
    const int warp = threadIdx.x >> 5;
    const int l    = threadIdx.x & 31;
    const int b    = blockIdx.x * NWARPS + warp;
    const bool hi  = (l < GG - 32);                  // l < 17

    float tot = 0.0f;

    if (b < N) {
        const float* bb = bbox  + (size_t)b * (5 * GG);
        const float* bp = bboxp + (size_t)b * (15 * GG);

        // ---------- batch 1: probs + q channels + cls (all independent) ----------
        float p0  = bb[l];
        float p1  = hi ? bb[l + 32] : 0.0f;
        float q0a = bp[l],          q1a = hi ? bp[l + 32]         : 0.5f;
        float q0b = bp[5*GG + l],   q1b = hi ? bp[5*GG + l + 32]  : 0.5f;
        float q0c = bp[10*GG + l],  q1c = hi ? bp[10*GG + l + 32] : 0.5f;

        float c0 = 0.f, c1 = 0.f; int y = 1;
        if (l == 0) {
            float2 cc = *(const float2*)(clsp + 2 * (size_t)b);
            c0 = cc.x; c1 = cc.y;
            y  = cls32[2 * b];
        }

        // ---------- batch 2: stream gather-channels fully (independent of m) ----
        // bb ch1-4 (gt), bp ch1-4 (anchor0), bp ch6-9 (anchor1)
        float u0[12], u1[12];
        #pragma unroll
        for (int c = 0; c < 4; c++) {             // bb channels 1..4
            const float* base = bb + (c + 1) * GG;
            u0[c] = base[l];  u1[c] = hi ? base[l + 32] : 0.0f;
        }
        #pragma unroll
        for (int c = 0; c < 4; c++) {             // bp channels 1..4
            const float* base = bp + (c + 1) * GG;
            u0[4 + c] = base[l];  u1[4 + c] = hi ? base[l + 32] : 0.0f;
        }
        #pragma unroll
        for (int c = 0; c < 4; c++) {             // bp channels 6..9
            const float* base = bp + (c + 6) * GG;
            u0[8 + c] = base[l];  u1[8 + c] = hi ? base[l + 32] : 0.0f;
        }

        // ---------- argmax over probs (exact, first-occurrence ties) ----------
        const unsigned w0 = __float_as_uint(p0);
        const unsigned w1 = hi ? __float_as_uint(p1) : 0u;
        const unsigned vmax = __reduce_max_sync(FULL, w0 > w1 ? w0 : w1);
        const unsigned bal0 = __ballot_sync(FULL, w0 == vmax);
        const unsigned bal1 = __ballot_sync(FULL, w1 == vmax);
        const int m    = bal0 ? (__ffs(bal0) - 1) : (32 + __ffs(bal1) - 1);
        const int msel = m & 31;
        const bool mhi = (m >= 32);

        // ---------- extract cell-m values via shuffles (no memory) ----------
        float ex[12];
        #pragma unroll
        for (int c = 0; c < 12; c++)
            ex[c] = __shfl_sync(FULL, mhi ? u1[c] : u0[c], msel);
        const float gt1 = ex[0], gt2 = ex[1], gt3 = ex[2], gt4 = ex[3];

        // ---------- batch 3: bp ch11-14 (anchor2), then extract ----------
        float t0[4], t1[4];
        #pragma unroll
        for (int c = 0; c < 4; c++) {
            const float* base = bp + (c + 11) * GG;
            t0[c] = base[l];  t1[c] = hi ? base[l + 32] : 0.0f;
        }
        float a2v[4];
        #pragma unroll
        for (int c = 0; c < 4; c++)
            a2v[c] = __shfl_sync(FULL, mhi ? t1[c] : t0[c], msel);

        // ---------- BCE stream part: sum of -log(1-q) via product ----------
        float P = (1.0f - q0a) * (1.0f - q0b) * (1.0f - q0c);
        if (hi) P *= (1.0f - q1a) * (1.0f - q1b) * (1.0f - q1c);
        float s = -__logf(P);

        // ---------- IoU for 3 anchors (uniform values, all lanes) ----------
        const float jf  = (float)(m % GDIM);
        const float if_ = (float)(m / GDIM);
        const float inv7 = 1.0f / 7.0f;
        const float tx  = (gt1 + jf)  * inv7;
        const float ty  = (gt2 + if_) * inv7;
        const float tx1 = tx - gt3 * 0.5f, tx2 = tx + gt3 * 0.5f;
        const float ty1 = ty - gt4 * 0.5f, ty2 = ty + gt4 * 0.5f;
        const float tarea = (tx2 - tx1) * (ty2 - ty1);

        int best = 0; float best_iou = -1e30f;
        float bx = 0.f, by = 0.f, bw = 0.f, bh = 0.f;
        #pragma unroll
        for (int a = 0; a < 3; a++) {
            const float v1x = (a < 2) ? ex[4 + 4*a + 0] : a2v[0];
            const float v2x = (a < 2) ? ex[4 + 4*a + 1] : a2v[1];
            const float v3x = (a < 2) ? ex[4 + 4*a + 2] : a2v[2];
            const float v4x = (a < 2) ? ex[4 + 4*a + 3] : a2v[3];
            const float ax  = (v1x + jf)  * inv7;
            const float ay  = (v2x + if_) * inv7;
            const float ax1 = ax - v3x * 0.5f, ax2 = ax + v3x * 0.5f;
            const float ay1 = ay - v4x * 0.5f, ay2 = ay + v4x * 0.5f;
            float iw = fmaxf(fminf(ax2, tx2) - fmaxf(ax1, tx1), 0.0f);
            float ih = fmaxf(fminf(ay2, ty2) - fmaxf(ay1, ty1), 0.0f);
            float inter = iw * ih;
            float uni   = (ax2 - ax1) * (ay2 - ay1) + tarea - inter;
            float iou   = __fdividef(inter, uni + 1e-9f);
            if (iou > best_iou) {                 // strict > keeps first index
                best_iou = iou; best = a;
                bx = v1x; by = v2x; bw = v3x; bh = v4x;
            }
        }

        // ---------- BCE correction: -p * (log q_best - log(1-q_best)) ----------
        float qb0 = (best == 0) ? q0a : (best == 1) ? q0b : q0c;
        s -= p0 * (__logf(qb0) - __logf(1.0f - qb0));
        if (hi) {
            float qb1 = (best == 0) ? q1a : (best == 1) ? q1b : q1c;
            s -= p1 * (__logf(qb1) - __logf(1.0f - qb1));
        }

        tot = s * (1.0f / ((float)N * 49.0f));

        // ---------- coord + size + CE (lane 0; values uniform) ----------
        if (l == 0) {
            float coord = -(gt1 * __logf(bx) + (1.0f - gt1) * __logf(1.0f - bx))
                        + -(gt2 * __logf(by) + (1.0f - gt2) * __logf(1.0f - by));
            float size_ = fabsf(__logf(bw) - __logf(gt3))
                        + fabsf(__logf(bh) - __logf(gt4));
            float mx  = fmaxf(c0, c1);
            float lse = mx + __logf(__expf(c0 - mx) + __expf(c1 - mx));
            float sel = (y == 1) ? c0 : c1;
            tot += coord + size_ + (lse - sel) * (1.0f / (float)N);
        }
    }

    // ---- warp reduce ----
    #pragma unroll
    for (int off = 16; off; off >>= 1)
        tot += __shfl_xor_sync(FULL, tot, off);

    // ---- block reduce -> one double atomic per block ----
    __shared__ float wsum[NWARPS];
    if (l == 0) wsum[warp] = tot;
    __syncthreads();
    if (threadIdx.x == 0) {
        float x = 0.0f;
        #pragma unroll
        for (int w = 0; w < NWARPS; w++) x += wsum[w];
        atomicAdd(&g_acc, (double)x);
        __threadfence();
        unsigned old = atomicInc(&g_count, gridDim.x - 1);
        if (old == gridDim.x - 1) {
            unsigned long long raw =
                atomicExch((unsigned long long*)&g_acc, 0ull);
            out[0] = (float)__longlong_as_double(raw);
        }
    }
}

extern "C" void kernel_launch(void* const* d_in, const int* in_sizes, int n_in,
                              void* d_out, int out_size)
{
    const float* bboxp = (const float*)d_in[0];     // (N,15,7,7)
    const float* clsp  = (const float*)d_in[1];     // (N,2)
    const float* bbox  = (const float*)d_in[2];     // (N,5,7,7)
    const int*   cls32 = (const int*)d_in[3];       // (N,) int64 -> int32 pairs

    const int N = in_sizes[3];
    const int nblocks = (N + NWARPS - 1) / NWARPS;

    loss_fused_kernel<<<nblocks, 32 * NWARPS>>>(bboxp, clsp, bbox, cls32,
                                                (float*)d_out, N);
}

// round 7
// speedup vs baseline: 1.4533x; 1.4533x over previous
#include <cuda_runtime.h>

#define GDIM 7
#define GG 49
#define NWARPS 8             // one sample per warp

__device__ double   g_acc   = 0.0;
__device__ unsigned g_count = 0u;

__global__ void __launch_bounds__(32 * NWARPS, 8)
loss_fused_kernel(const float* __restrict__ bboxp,   // (N,15,7,7)
                  const float* __restrict__ clsp,    // (N,2)
                  const float* __restrict__ bbox,    // (N,5,7,7)
                  const int*   __restrict__ cls32,   // (N,) int64 as int32 pairs
                  float* __restrict__ out,
                  int N)
{
    const unsigned FULL = 0xffffffffu;
    const int warp = threadIdx.x >> 5;
    const int l    = threadIdx.x & 31;
    const int b    = blockIdx.x * NWARPS + warp;

    float tot = 0.0f;

    if (b < N) {
        const float* bb = bbox  + (size_t)b * (5 * GG);
        const float* bp = bboxp + (size_t)b * (15 * GG);
        const bool hi = (l < GG - 32);                  // l < 17

        // ---- all independent streamed loads up front (full-line consumers) ----
        float p0  = bb[l];
        float p1  = hi ? bb[l + 32] : 0.0f;
        float q0a = bp[l],          q1a = hi ? bp[l + 32]         : 0.5f;
        float q0b = bp[5*GG + l],   q1b = hi ? bp[5*GG + l + 32]  : 0.5f;
        float q0c = bp[10*GG + l],  q1c = hi ? bp[10*GG + l + 32] : 0.5f;

        float c0 = 0.f, c1 = 0.f; int y = 1;
        if (l == 0) {
            float2 cc = *(const float2*)(clsp + 2 * (size_t)b);
            c0 = cc.x; c1 = cc.y;
            y  = cls32[2 * b];
        }

        // ---- exact argmax: REDUX on positive-float bits + ballots ----
        const unsigned w0 = __float_as_uint(p0);              // probs > 0
        const unsigned w1 = hi ? __float_as_uint(p1) : 0u;
        const unsigned vmax = __reduce_max_sync(FULL, w0 > w1 ? w0 : w1);
        const unsigned bal0 = __ballot_sync(FULL, w0 == vmax);
        const unsigned bal1 = __ballot_sync(FULL, w1 == vmax);
        const int m = bal0 ? (__ffs(bal0) - 1) : (32 + __ffs(bal1) - 1);
        const float jf  = (float)(m % GDIM);
        const float if_ = (float)(m / GDIM);

        // ---- dependent gather: 19 cell-m values, one per lane ----
        // Each lane hits its own 128B line; request only a 64B fetch from DRAM.
        float g = 0.0f;
        {
            const float* gptr;
            if (l < 15)       gptr = bp + l * GG + m;          // cell_pr ch 0..14
            else if (l < 19)  gptr = bb + (l - 14) * GG + m;   // cell_gt ch 1..4
            else              gptr = bp + m;                   // harmless dup of ch0
            asm volatile("ld.global.L2::64B.f32 %0, [%1];" : "=f"(g) : "l"(gptr));
        }

        // ---- independent log work overlaps the gather latency ----
        float P = (1.0f - q0a) * (1.0f - q0b) * (1.0f - q0c);
        if (hi) P *= (1.0f - q1a) * (1.0f - q1b) * (1.0f - q1c);
        float s = -__logf(P);                      // sum of -log(1-q), this lane

        // ---- broadcast gt; lanes 0..2 own one anchor each ----
        const float gt1 = __shfl_sync(FULL, g, 15);
        const float gt2 = __shfl_sync(FULL, g, 16);
        const float gt3 = __shfl_sync(FULL, g, 17);
        const float gt4 = __shfl_sync(FULL, g, 18);

        const int al = 5 * min(l, 2);
        const float a1 = __shfl_sync(FULL, g, al + 1);
        const float a2 = __shfl_sync(FULL, g, al + 2);
        const float a3 = __shfl_sync(FULL, g, al + 3);
        const float a4 = __shfl_sync(FULL, g, al + 4);

        // ---- IoU on lanes 0..2; winner via one packed REDUX ----
        const float inv7 = 1.0f / 7.0f;
        const float tx  = (gt1 + jf)  * inv7;
        const float ty  = (gt2 + if_) * inv7;
        const float tx1 = tx - gt3 * 0.5f, tx2 = tx + gt3 * 0.5f;
        const float ty1 = ty - gt4 * 0.5f, ty2 = ty + gt4 * 0.5f;
        const float tarea = (tx2 - tx1) * (ty2 - ty1);

        const float ax  = (a1 + jf)  * inv7;
        const float ay  = (a2 + if_) * inv7;
        const float ax1 = ax - a3 * 0.5f, ax2 = ax + a3 * 0.5f;
        const float ay1 = ay - a4 * 0.5f, ay2 = ay + a4 * 0.5f;
        float iw = fmaxf(fminf(ax2, tx2) - fmaxf(ax1, tx1), 0.0f);
        float ih = fmaxf(fminf(ay2, ty2) - fmaxf(ay1, ty1), 0.0f);
        float inter = iw * ih;
        float uni   = (ax2 - ax1) * (ay2 - ay1) + tarea - inter;
        float iou   = __fdividef(inter, uni + 1e-9f);

        // max of (iou bits | (3 - anchor)) -> best iou, first index on ties
        unsigned key = (l < 3) ? ((__float_as_uint(iou) & ~3u) | (3u - l)) : 0u;
        key = __reduce_max_sync(FULL, key);
        const int best = 3 - (int)(key & 3u);

        // ---- BCE correction for best anchor: -p * (log q - log(1-q)) ----
        float qb0 = (best == 0) ? q0a : (best == 1) ? q0b : q0c;
        s -= p0 * (__logf(qb0) - __logf(1.0f - qb0));
        if (hi) {
            float qb1 = (best == 0) ? q1a : (best == 1) ? q1b : q1c;
            s -= p1 * (__logf(qb1) - __logf(1.0f - qb1));
        }

        tot = s * (1.0f / ((float)N * 49.0f));

        // ---- coord + size computed on the winning anchor's lane ----
        if (l == best) {
            float coord = -(gt1 * __logf(a1) + (1.0f - gt1) * __logf(1.0f - a1))
                        + -(gt2 * __logf(a2) + (1.0f - gt2) * __logf(1.0f - a2));
            float size_ = fabsf(__logf(a3) - __logf(gt3))
                        + fabsf(__logf(a4) - __logf(gt4));
            tot += coord + size_;
        }

        // ---- CE on lane 0 ----
        if (l == 0) {
            float mx  = fmaxf(c0, c1);
            float lse = mx + __logf(__expf(c0 - mx) + __expf(c1 - mx));
            float sel = (y == 1) ? c0 : c1;
            tot += (lse - sel) * (1.0f / (float)N);
        }
    }

    // ---- warp reduce ----
    #pragma unroll
    for (int off = 16; off; off >>= 1)
        tot += __shfl_xor_sync(FULL, tot, off);

    // ---- block reduce -> one double atomic per block ----
    __shared__ float wsum[NWARPS];
    if (l == 0) wsum[warp] = tot;
    __syncthreads();
    if (threadIdx.x == 0) {
        float x = 0.0f;
        #pragma unroll
        for (int w = 0; w < NWARPS; w++) x += wsum[w];
        atomicAdd(&g_acc, (double)x);
        __threadfence();
        unsigned old = atomicInc(&g_count, gridDim.x - 1);
        if (old == gridDim.x - 1) {
            unsigned long long raw =
                atomicExch((unsigned long long*)&g_acc, 0ull);
            out[0] = (float)__longlong_as_double(raw);
        }
    }
}

extern "C" void kernel_launch(void* const* d_in, const int* in_sizes, int n_in,
                              void* d_out, int out_size)
{
    const float* bboxp = (const float*)d_in[0];     // (N,15,7,7)
    const float* clsp  = (const float*)d_in[1];     // (N,2)
    const float* bbox  = (const float*)d_in[2];     // (N,5,7,7)
    const int*   cls32 = (const int*)d_in[3];       // (N,) int64 -> int32 pairs

    const int N = in_sizes[3];
    const int nblocks = (N + NWARPS - 1) / NWARPS;

    loss_fused_kernel<<<nblocks, 32 * NWARPS>>>(bboxp, clsp, bbox, cls32,
                                                (float*)d_out, N);
}

// round 8
// speedup vs baseline: 1.5217x; 1.0471x over previous
#include <cuda_runtime.h>

#define GDIM 7
#define GG 49
#define NWARPS 4             // one sample per warp, 128-thread blocks

__device__ double   g_acc   = 0.0;
__device__ unsigned g_count = 0u;

__global__ void __launch_bounds__(32 * NWARPS, 16)
loss_fused_kernel(const float* __restrict__ bboxp,   // (N,15,7,7)
                  const float* __restrict__ clsp,    // (N,2)
                  const float* __restrict__ bbox,    // (N,5,7,7)
                  const int*   __restrict__ cls32,   // (N,) int64 as int32 pairs
                  float* __restrict__ out,
                  int N)
{
    const unsigned FULL = 0xffffffffu;
    const int warp = threadIdx.x >> 5;
    const int l    = threadIdx.x & 31;
    const int b    = blockIdx.x * NWARPS + warp;

    float tot = 0.0f;

    if (b < N) {
        const float* bb = bbox  + (size_t)b * (5 * GG);
        const float* bp = bboxp + (size_t)b * (15 * GG);
        const bool hi = (l < GG - 32);                  // l < 17

        // ---- independent streamed loads up front ----
        float p0  = bb[l];
        float p1  = hi ? bb[l + 32] : 0.0f;
        float q0a = bp[l],          q1a = hi ? bp[l + 32]         : 0.5f;
        float q0b = bp[5*GG + l],   q1b = hi ? bp[5*GG + l + 32]  : 0.5f;
        float q0c = bp[10*GG + l],  q1c = hi ? bp[10*GG + l + 32] : 0.5f;

        float c0 = 0.f, c1 = 0.f; int y = 1;
        if (l == 0) {
            float2 cc = *(const float2*)(clsp + 2 * (size_t)b);
            c0 = cc.x; c1 = cc.y;
            y  = cls32[2 * b];
        }

        // ---- exact argmax: REDUX on positive-float bits + ballots ----
        const unsigned w0 = __float_as_uint(p0);              // probs > 0
        const unsigned w1 = hi ? __float_as_uint(p1) : 0u;
        const unsigned vmax = __reduce_max_sync(FULL, w0 > w1 ? w0 : w1);
        const unsigned bal0 = __ballot_sync(FULL, w0 == vmax);
        const unsigned bal1 = __ballot_sync(FULL, w1 == vmax);
        const int m = bal0 ? (__ffs(bal0) - 1) : (32 + __ffs(bal1) - 1);
        const float jf  = (float)(m % GDIM);
        const float if_ = (float)(m / GDIM);

        // ---- dependent gather: exactly 16 useful cell-m values ----
        // lanes 0..11  -> bp channel 5*(l/4) + (l%4) + 1   (anchor boxes)
        // lanes 12..15 -> bb channel (l-11)                (gt box)
        // lanes >= 16  -> no load
        float g = 0.0f;
        if (l < 16) {
            const float* gptr = (l < 12)
                ? bp + ((l >> 2) * 5 + (l & 3) + 1) * GG + m
                : bb + (l - 11) * GG + m;
            asm volatile("ld.global.L2::64B.f32 %0, [%1];" : "=f"(g) : "l"(gptr));
        }

        // ---- independent log work overlaps the gather latency ----
        float P = (1.0f - q0a) * (1.0f - q0b) * (1.0f - q0c);
        if (hi) P *= (1.0f - q1a) * (1.0f - q1b) * (1.0f - q1c);
        float s = -__logf(P);                      // sum of -log(1-q), this lane

        // ---- broadcast gt; lanes 0..2 own one anchor each ----
        const float gt1 = __shfl_sync(FULL, g, 12);
        const float gt2 = __shfl_sync(FULL, g, 13);
        const float gt3 = __shfl_sync(FULL, g, 14);
        const float gt4 = __shfl_sync(FULL, g, 15);

        const int al = 4 * min(l, 2);
        const float a1 = __shfl_sync(FULL, g, al + 0);
        const float a2 = __shfl_sync(FULL, g, al + 1);
        const float a3 = __shfl_sync(FULL, g, al + 2);
        const float a4 = __shfl_sync(FULL, g, al + 3);

        // ---- IoU on lanes 0..2; winner via one packed REDUX ----
        const float inv7 = 1.0f / 7.0f;
        const float tx  = (gt1 + jf)  * inv7;
        const float ty  = (gt2 + if_) * inv7;
        const float tx1 = tx - gt3 * 0.5f, tx2 = tx + gt3 * 0.5f;
        const float ty1 = ty - gt4 * 0.5f, ty2 = ty + gt4 * 0.5f;
        const float tarea = (tx2 - tx1) * (ty2 - ty1);

        const float ax  = (a1 + jf)  * inv7;
        const float ay  = (a2 + if_) * inv7;
        const float ax1 = ax - a3 * 0.5f, ax2 = ax + a3 * 0.5f;
        const float ay1 = ay - a4 * 0.5f, ay2 = ay + a4 * 0.5f;
        float iw = fmaxf(fminf(ax2, tx2) - fmaxf(ax1, tx1), 0.0f);
        float ih = fmaxf(fminf(ay2, ty2) - fmaxf(ay1, ty1), 0.0f);
        float inter = iw * ih;
        float uni   = (ax2 - ax1) * (ay2 - ay1) + tarea - inter;
        float iou   = __fdividef(inter, uni + 1e-9f);

        // max of (iou bits | (3 - anchor)) -> best iou, first index on ties
        unsigned key = (l < 3) ? ((__float_as_uint(iou) & ~3u) | (3u - l)) : 0u;
        key = __reduce_max_sync(FULL, key);
        const int best = 3 - (int)(key & 3u);

        // ---- BCE correction for best anchor: -p * (log q - log(1-q)) ----
        float qb0 = (best == 0) ? q0a : (best == 1) ? q0b : q0c;
        s -= p0 * (__logf(qb0) - __logf(1.0f - qb0));
        if (hi) {
            float qb1 = (best == 0) ? q1a : (best == 1) ? q1b : q1c;
            s -= p1 * (__logf(qb1) - __logf(1.0f - qb1));
        }

        tot = s * (1.0f / ((float)N * 49.0f));

        // ---- coord + size computed on the winning anchor's lane ----
        if (l == best) {
            float coord = -(gt1 * __logf(a1) + (1.0f - gt1) * __logf(1.0f - a1))
                        + -(gt2 * __logf(a2) + (1.0f - gt2) * __logf(1.0f - a2));
            float size_ = fabsf(__logf(a3) - __logf(gt3))
                        + fabsf(__logf(a4) - __logf(gt4));
            tot += coord + size_;
        }

        // ---- CE on lane 0 ----
        if (l == 0) {
            float mx  = fmaxf(c0, c1);
            float lse = mx + __logf(__expf(c0 - mx) + __expf(c1 - mx));
            float sel = (y == 1) ? c0 : c1;
            tot += (lse - sel) * (1.0f / (float)N);
        }
    }

    // ---- warp reduce ----
    #pragma unroll
    for (int off = 16; off; off >>= 1)
        tot += __shfl_xor_sync(FULL, tot, off);

    // ---- block reduce -> one double atomic per block ----
    __shared__ float wsum[NWARPS];
    if (l == 0) wsum[warp] = tot;
    __syncthreads();
    if (threadIdx.x == 0) {
        float x = 0.0f;
        #pragma unroll
        for (int w = 0; w < NWARPS; w++) x += wsum[w];
        atomicAdd(&g_acc, (double)x);
        __threadfence();
        unsigned old = atomicInc(&g_count, gridDim.x - 1);
        if (old == gridDim.x - 1) {
            unsigned long long raw =
                atomicExch((unsigned long long*)&g_acc, 0ull);
            out[0] = (float)__longlong_as_double(raw);
        }
    }
}

extern "C" void kernel_launch(void* const* d_in, const int* in_sizes, int n_in,
                              void* d_out, int out_size)
{
    const float* bboxp = (const float*)d_in[0];     // (N,15,7,7)
    const float* clsp  = (const float*)d_in[1];     // (N,2)
    const float* bbox  = (const float*)d_in[2];     // (N,5,7,7)
    const int*   cls32 = (const int*)d_in[3];       // (N,) int64 -> int32 pairs

    const int N = in_sizes[3];
    const int nblocks = (N + NWARPS - 1) / NWARPS;

    loss_fused_kernel<<<nblocks, 32 * NWARPS>>>(bboxp, clsp, bbox, cls32,
                                                (float*)d_out, N);
}